// round 16
// baseline (speedup 1.0000x reference)
#include <cuda_runtime.h>
#include <cuda_bf16.h>
#include <stdint.h>

// MinibatchDiscrimination fused, phase-pipelined:
//  Phase A: GEMM sub0.   Phase B: GEMM sub1 || pairwise sub0.   Phase C: pairwise sub1.
// All 16 warps uniform. bf16 mma.sync GEMM, cp.async T stream, bf16x2 pairwise + guarded exp.

#define NSAMP   16384
#define FDIM    256
#define NCOLS   512
#define NK      32
#define KD      16
#define OUTF    288
#define SPB     64
#define SSP     32
#define NBLK    (NSAMP/SPB)   // 256
#define NT      512
#define KC      32
#define NCHT    16            // 2 subtiles x 8 chunks
#define NBUF    3

#define XST 264
#define TST 520
#define MST 520
#define XS_OFF 0
#define MS_OFF (SPB*XST)               // 16896 halfs
#define MSBUF  (SSP*MST)               // 16640 (single buffer, reused)
#define TS_OFF (MS_OFF + MSBUF)        // 33536
#define TSBUF  (KC*TST)                // 16640
#define SMEM_HALFS (TS_OFF + NBUF*TSBUF)  // 83456
#define SMEM_BYTES (SMEM_HALFS*2)         // 166912 B -> 1 CTA/SM

__device__ __nv_bfloat16 g_Tbf[FDIM * NCOLS];   // 256 KB

__global__ void convT_kernel(const float* __restrict__ T) {
    int i = blockIdx.x * blockDim.x + threadIdx.x;
    #pragma unroll
    for (int j = 0; j < 2; j++) {
        float4 v = ((const float4*)T)[i + j * 16384];
        *(__nv_bfloat162*)&g_Tbf[(i + j * 16384) * 4]     = __floats2bfloat162_rn(v.x, v.y);
        *(__nv_bfloat162*)&g_Tbf[(i + j * 16384) * 4 + 2] = __floats2bfloat162_rn(v.z, v.w);
    }
}

__device__ __forceinline__ unsigned int smem_addr(const void* p) {
    return (unsigned int)__cvta_generic_to_shared(p);
}
__device__ __forceinline__ void cp16(unsigned int dst, const void* src) {
    asm volatile("cp.async.cg.shared.global [%0], [%1], 16;" :: "r"(dst), "l"(src));
}
__device__ __forceinline__ void ldmatrix_x4(unsigned int* r, unsigned int addr) {
    asm volatile("ldmatrix.sync.aligned.m8n8.x4.shared.b16 {%0,%1,%2,%3}, [%4];"
                 : "=r"(r[0]), "=r"(r[1]), "=r"(r[2]), "=r"(r[3]) : "r"(addr));
}
__device__ __forceinline__ void ldmatrix_x4_trans(unsigned int* r, unsigned int addr) {
    asm volatile("ldmatrix.sync.aligned.m8n8.x4.trans.shared.b16 {%0,%1,%2,%3}, [%4];"
                 : "=r"(r[0]), "=r"(r[1]), "=r"(r[2]), "=r"(r[3]) : "r"(addr));
}
__device__ __forceinline__ void mma_bf16(float* c, const unsigned int* a, const unsigned int* b) {
    asm volatile("mma.sync.aligned.m16n8k16.row.col.f32.bf16.bf16.f32 "
                 "{%0,%1,%2,%3}, {%4,%5,%6,%7}, {%8,%9}, {%0,%1,%2,%3};"
                 : "+f"(c[0]), "+f"(c[1]), "+f"(c[2]), "+f"(c[3])
                 : "r"(a[0]), "r"(a[1]), "r"(a[2]), "r"(a[3]), "r"(b[0]), "r"(b[1]));
}

extern __shared__ __nv_bfloat16 sm[];

__device__ __forceinline__ void stage_T_chunk(int gc, int t) {
    const char* src = (const char*)(g_Tbf + (long)(gc & 7) * KC * NCOLS);
    unsigned int dst = smem_addr(sm + TS_OFF + (gc % NBUF) * TSBUF);
    #pragma unroll
    for (int i = 0; i < 4; i++) {
        int g = t + i * NT;
        int r = g >> 6, c16 = g & 63;
        cp16(dst + (r * TST + c16 * 8) * 2, src + r * 1024 + c16 * 16);
    }
    asm volatile("cp.async.commit_group;");
}

__device__ __forceinline__ void gemm_chunk(float (*acc)[4], const __nv_bfloat16* xs,
                                           int sub, int gc, int wm, int n0,
                                           int arow, int acg, int brow_in, int bcol_in) {
    const __nv_bfloat16* Tb = sm + TS_OFF + (gc % NBUF) * TSBUF;
    #pragma unroll
    for (int ks = 0; ks < 2; ks++) {
        const int k0 = (gc & 7) * KC + ks * 16;
        unsigned int a[4];
        ldmatrix_x4(a, smem_addr(&xs[(sub * 32 + wm * 16 + arow) * XST + k0 + acg * 8]));
        #pragma unroll
        for (int ntp = 0; ntp < 4; ntp++) {
            unsigned int b[4];
            ldmatrix_x4_trans(b, smem_addr(&Tb[(ks * 16 + brow_in) * TST
                                               + n0 + ntp * 16 + bcol_in]));
            mma_bf16(acc[2 * ntp],     a, b);
            mma_bf16(acc[2 * ntp + 1], a, b + 2);
        }
    }
}

__device__ __forceinline__ void store_Ms(float (*acc)[4], __nv_bfloat16* Msb,
                                         int wm, int n0, int lane) {
    const int r = lane >> 2, c2 = (lane & 3) * 2;
    #pragma unroll
    for (int nt = 0; nt < 8; nt++) {
        unsigned int p01 = __byte_perm(__float_as_uint(acc[nt][0]),
                                       __float_as_uint(acc[nt][1]), 0x7632);
        unsigned int p23 = __byte_perm(__float_as_uint(acc[nt][2]),
                                       __float_as_uint(acc[nt][3]), 0x7632);
        *(unsigned int*)&Msb[(wm * 16 + r)     * MST + n0 + nt * 8 + c2] = p01;
        *(unsigned int*)&Msb[(wm * 16 + r + 8) * MST + n0 + nt * 8 + c2] = p23;
    }
}

__device__ __forceinline__ void pair_iters8(__nv_bfloat162* a8, const __nv_bfloat162* v,
                                            const __nv_bfloat16* Mrow, int k2base) {
    #pragma unroll
    for (int it = 0; it < 8; it++) {
        const int k2 = k2base + it;
        __align__(16) __nv_bfloat162 m[8];
        *(uint4*)&m[0] = *(const uint4*)&Mrow[k2 * KD];      // broadcast
        *(uint4*)&m[4] = *(const uint4*)&Mrow[k2 * KD + 8];
        #pragma unroll
        for (int j = 0; j < 8; j++)
            a8[j] = __hadd2(a8[j], __habs2(__hsub2(m[j], v[j])));
    }
}

__device__ __forceinline__ float pair_final(const __nv_bfloat162* a8) {
    __nv_bfloat162 mn2 = a8[0];
    #pragma unroll
    for (int j = 1; j < 8; j++) mn2 = __hmin2(mn2, a8[j]);
    float2 mnf = __bfloat1622float2(mn2);
    float mn = fminf(mnf.x, mnf.y);
    float facc = 0.f;
    if (__any_sync(0xffffffffu, mn < 100.0f)) {   // exp(-100)=3.7e-44: faithful, ~never taken
        #pragma unroll
        for (int j = 0; j < 8; j++) {
            float2 f = __bfloat1622float2(a8[j]);
            if (f.x < 100.0f) facc += __expf(-f.x);
            if (f.y < 100.0f) facc += __expf(-f.y);
        }
    }
    return facc;
}

__global__ void __launch_bounds__(NT, 1) mbd_kernel(
    const float* __restrict__ x,
    float* __restrict__ out)
{
    __nv_bfloat16* xs  = sm + XS_OFF;
    __nv_bfloat16* Msb = sm + MS_OFF;

    const int t = threadIdx.x;
    const int warp = t >> 5;
    const int lane = t & 31;
    const long sbase = (long)blockIdx.x * SPB;

    stage_T_chunk(0, t);
    stage_T_chunk(1, t);

    // stage x (both subtiles) -> out copy + xs bf16 (PRMT trunc); 4096 float4, 8/thread
    {
        const float4* xg = (const float4*)(x + sbase * FDIM);
        #pragma unroll
        for (int i = 0; i < 8; i++) {
            int idx = t + i * NT;
            int s = idx >> 6, c4 = idx & 63;
            float4 v = xg[idx];
            *(float4*)&out[(sbase + s) * OUTF + c4 * 4] = v;
            unsigned int p0 = __byte_perm(__float_as_uint(v.x), __float_as_uint(v.y), 0x7632);
            unsigned int p1 = __byte_perm(__float_as_uint(v.z), __float_as_uint(v.w), 0x7632);
            *(uint2*)&xs[s * XST + c4 * 4] = make_uint2(p0, p1);
        }
    }

    const int wm = warp & 1;
    const int n0 = (warp >> 1) * 64;
    const int arow = lane & 15;
    const int acg  = lane >> 4;
    const int brow_in = ((lane >> 3) & 1) * 8 + (lane & 7);
    const int bcol_in = (lane >> 4) * 8;

    float acc[8][4];
    #pragma unroll
    for (int nt = 0; nt < 8; nt++)
        #pragma unroll
        for (int j = 0; j < 4; j++) acc[nt][j] = 0.f;

    // ---- Phase A: GEMM sub0 ----
    #pragma unroll 1
    for (int gc = 0; gc < 8; gc++) {
        asm volatile("cp.async.wait_group 1;");
        __syncthreads();
        if (gc + 2 < NCHT) stage_T_chunk(gc + 2, t);
        gemm_chunk(acc, xs, 0, gc, wm, n0, arow, acg, brow_in, bcol_in);
    }
    store_Ms(acc, Msb, wm, n0, lane);        // published by the gc=8 barrier below
    #pragma unroll
    for (int nt = 0; nt < 8; nt++)
        #pragma unroll
        for (int j = 0; j < 4; j++) acc[nt][j] = 0.f;

    // ---- Phase B: GEMM sub1 || pairwise sub0 ----
    __nv_bfloat162 v8[8], a8[8];
    #pragma unroll 1
    for (int gc = 8; gc < 16; gc++) {
        if (gc < 15) asm volatile("cp.async.wait_group 1;");
        else         asm volatile("cp.async.wait_group 0;");
        __syncthreads();
        if (gc + 2 < NCHT) stage_T_chunk(gc + 2, t);
        gemm_chunk(acc, xs, 1, gc, wm, n0, arow, acg, brow_in, bcol_in);

        const int ch = gc - 8;
        const int ps = warp * 2 + (ch >> 2);             // 2 samples/warp, 4 chunks each
        const __nv_bfloat16* Mrow = Msb + ps * MST;
        if ((ch & 3) == 0) {
            *(uint4*)&v8[0] = *(const uint4*)&Mrow[lane * KD];
            *(uint4*)&v8[4] = *(const uint4*)&Mrow[lane * KD + 8];
            const __nv_bfloat162 z2 = __floats2bfloat162_rn(0.f, 0.f);
            #pragma unroll
            for (int j = 0; j < 8; j++) a8[j] = z2;
        }
        pair_iters8(a8, v8, Mrow, (ch & 3) * 8);
        if ((ch & 3) == 3)
            out[(sbase + ps) * OUTF + FDIM + lane] = pair_final(a8);
    }

    // ---- Phase C: pairwise sub1 (reuse Ms buffer) ----
    __syncthreads();                          // all sub0 pairwise reads done
    store_Ms(acc, Msb, wm, n0, lane);
    __syncthreads();

    #pragma unroll 1
    for (int si = 0; si < 2; si++) {
        const int s = warp * 2 + si;
        const __nv_bfloat16* Mrow = Msb + s * MST;
        *(uint4*)&v8[0] = *(const uint4*)&Mrow[lane * KD];
        *(uint4*)&v8[4] = *(const uint4*)&Mrow[lane * KD + 8];
        const __nv_bfloat162 z2 = __floats2bfloat162_rn(0.f, 0.f);
        #pragma unroll
        for (int j = 0; j < 8; j++) a8[j] = z2;
        #pragma unroll
        for (int kb = 0; kb < 4; kb++)
            pair_iters8(a8, v8, Mrow, kb * 8);
        out[(sbase + SSP + s) * OUTF + FDIM + lane] = pair_final(a8);
    }
}

extern "C" void kernel_launch(void* const* d_in, const int* in_sizes, int n_in,
                              void* d_out, int out_size)
{
    const float* x = (const float*)d_in[0];
    const float* T = (const float*)d_in[1];
    if (n_in >= 2 && in_sizes[0] < in_sizes[1]) {
        const float* tmp = x; x = T; T = tmp;
    }
    float* out = (float*)d_out;

    cudaFuncSetAttribute(mbd_kernel,
                         cudaFuncAttributeMaxDynamicSharedMemorySize,
                         SMEM_BYTES);

    convT_kernel<<<64, 256>>>(T);
    mbd_kernel<<<NBLK, NT, SMEM_BYTES>>>(x, out);
}

// round 17
// speedup vs baseline: 1.2456x; 1.2456x over previous
#include <cuda_runtime.h>
#include <cuda_bf16.h>
#include <stdint.h>

// MinibatchDiscrimination fused: x[32,512,256] f32, T[256,512] f32 -> out[32,512,288] f32
// Round-14 baseline (best: 51.9us) with ONE change: pairwise L1 uses the max/min
// pipe split (P += hmax2, Q += hmin2, a = P - Q) to move half the pairwise ops
// off the fma pipe onto the alu pipe.

#define NSAMP   16384
#define FDIM    256
#define NCOLS   512
#define NK      32
#define KD      16
#define OUTF    288
#define SPB     64
#define NBLK    (NSAMP/SPB)   // 256
#define NT      512
#define KC      32
#define NCH     (FDIM/KC)     // 8
#define NBUF    3

#define XST 264
#define TST 520
#define MST 520
#define XS_OFF 0
#define TS_OFF (SPB*XST)              // 16896 halfs
#define TSBUF  (KC*TST)               // 16640 halfs
#define SMEM_HALFS (TS_OFF + NBUF*TSBUF)   // 66816
#define SMEM_BYTES (SMEM_HALFS*2)          // 133632 B -> 1 CTA/SM

__device__ __nv_bfloat16 g_Tbf[FDIM * NCOLS];   // 256 KB

__global__ void convT_kernel(const float* __restrict__ T) {
    int i = blockIdx.x * blockDim.x + threadIdx.x;   // float4 index
    float4 v = ((const float4*)T)[i];
    *(__nv_bfloat162*)&g_Tbf[i * 4]     = __floats2bfloat162_rn(v.x, v.y);
    *(__nv_bfloat162*)&g_Tbf[i * 4 + 2] = __floats2bfloat162_rn(v.z, v.w);
}

__device__ __forceinline__ unsigned int smem_addr(const void* p) {
    return (unsigned int)__cvta_generic_to_shared(p);
}
__device__ __forceinline__ void cp16(unsigned int dst, const void* src) {
    asm volatile("cp.async.cg.shared.global [%0], [%1], 16;" :: "r"(dst), "l"(src));
}
__device__ __forceinline__ void ldmatrix_x4(unsigned int* r, unsigned int addr) {
    asm volatile("ldmatrix.sync.aligned.m8n8.x4.shared.b16 {%0,%1,%2,%3}, [%4];"
                 : "=r"(r[0]), "=r"(r[1]), "=r"(r[2]), "=r"(r[3]) : "r"(addr));
}
__device__ __forceinline__ void ldmatrix_x4_trans(unsigned int* r, unsigned int addr) {
    asm volatile("ldmatrix.sync.aligned.m8n8.x4.trans.shared.b16 {%0,%1,%2,%3}, [%4];"
                 : "=r"(r[0]), "=r"(r[1]), "=r"(r[2]), "=r"(r[3]) : "r"(addr));
}
__device__ __forceinline__ void mma_bf16(float* c, const unsigned int* a, const unsigned int* b) {
    asm volatile("mma.sync.aligned.m16n8k16.row.col.f32.bf16.bf16.f32 "
                 "{%0,%1,%2,%3}, {%4,%5,%6,%7}, {%8,%9}, {%0,%1,%2,%3};"
                 : "+f"(c[0]), "+f"(c[1]), "+f"(c[2]), "+f"(c[3])
                 : "r"(a[0]), "r"(a[1]), "r"(a[2]), "r"(a[3]), "r"(b[0]), "r"(b[1]));
}

extern __shared__ __nv_bfloat16 sm[];

__global__ void __launch_bounds__(NT, 1) mbd_kernel(
    const float* __restrict__ x,
    float* __restrict__ out)
{
    __nv_bfloat16* xs = sm + XS_OFF;
    __nv_bfloat16* Ms = sm;            // alias over xs+Tbuf0 (dead at epilogue)

    const int t = threadIdx.x;
    const int warp = t >> 5;           // 0..15
    const int lane = t & 31;
    const long sbase = (long)blockIdx.x * SPB;

    // ---- prefetch T chunks 0,1 (2048 granules of 16B each; 4/thread) ----
    #pragma unroll
    for (int c = 0; c < 2; c++) {
        const char* src = (const char*)(g_Tbf + (long)c * KC * NCOLS);
        unsigned int dst = smem_addr(sm + TS_OFF + c * TSBUF);
        #pragma unroll
        for (int i = 0; i < 4; i++) {
            int g = t + i * NT;
            int r = g >> 6, c16 = g & 63;
            cp16(dst + (r * TST + c16 * 8) * 2, src + r * 1024 + c16 * 16);
        }
        asm volatile("cp.async.commit_group;");
    }

    // ---- stage x -> out (copy) and -> xs (bf16) : 4096 float4, 8/thread ----
    {
        const float4* xg = (const float4*)(x + sbase * FDIM);
        #pragma unroll
        for (int i = 0; i < 8; i++) {
            int idx = t + i * NT;
            int s = idx >> 6, c4 = idx & 63;
            float4 v = xg[idx];
            *(float4*)&out[(sbase + s) * OUTF + c4 * 4] = v;
            *(__nv_bfloat162*)&xs[s * XST + c4 * 4]     = __floats2bfloat162_rn(v.x, v.y);
            *(__nv_bfloat162*)&xs[s * XST + c4 * 4 + 2] = __floats2bfloat162_rn(v.z, v.w);
        }
    }

    // ---- GEMM: warp w -> rows (w&1)*32..+31, cols (w>>1)*64..+63 ----
    const int wm = warp & 1;
    const int n0 = (warp >> 1) * 64;
    float acc[2][8][4];
    #pragma unroll
    for (int mt = 0; mt < 2; mt++)
        #pragma unroll
        for (int nt = 0; nt < 8; nt++)
            #pragma unroll
            for (int j = 0; j < 4; j++) acc[mt][nt][j] = 0.f;

    const int arow = lane & 15;
    const int acg  = lane >> 4;
    const int brow_in = ((lane >> 3) & 1) * 8 + (lane & 7);  // k within 16
    const int bcol_in = (lane >> 4) * 8;                     // +0 / +8

    #pragma unroll 1
    for (int ch = 0; ch < NCH; ch++) {
        if (ch < NCH - 1) asm volatile("cp.async.wait_group 1;");
        else              asm volatile("cp.async.wait_group 0;");
        __syncthreads();   // chunk ch visible; all warps done with buf[(ch-1)%3]

        if (ch + 2 < NCH) {
            const int c = ch + 2;
            const char* src = (const char*)(g_Tbf + (long)c * KC * NCOLS);
            unsigned int dst = smem_addr(sm + TS_OFF + (c % NBUF) * TSBUF);
            #pragma unroll
            for (int i = 0; i < 4; i++) {
                int g = t + i * NT;
                int r = g >> 6, c16 = g & 63;
                cp16(dst + (r * TST + c16 * 8) * 2, src + r * 1024 + c16 * 16);
            }
            asm volatile("cp.async.commit_group;");
        }

        const __nv_bfloat16* Tb = sm + TS_OFF + (ch % NBUF) * TSBUF;
        #pragma unroll
        for (int ks = 0; ks < 2; ks++) {
            const int k0 = ch * KC + ks * 16;
            unsigned int a[2][4];
            ldmatrix_x4(a[0], smem_addr(&xs[(wm * 32 + arow)      * XST + k0 + acg * 8]));
            ldmatrix_x4(a[1], smem_addr(&xs[(wm * 32 + 16 + arow) * XST + k0 + acg * 8]));
            #pragma unroll
            for (int ntp = 0; ntp < 4; ntp++) {
                unsigned int b[4];
                ldmatrix_x4_trans(b, smem_addr(&Tb[(ks * 16 + brow_in) * TST
                                                   + n0 + ntp * 16 + bcol_in]));
                mma_bf16(acc[0][2 * ntp],     a[0], b);
                mma_bf16(acc[1][2 * ntp],     a[1], b);
                mma_bf16(acc[0][2 * ntp + 1], a[0], b + 2);
                mma_bf16(acc[1][2 * ntp + 1], a[1], b + 2);
            }
        }
    }

    // ---- store M (bf16) to smem (alias; all xs/Tbuf0 reads done) ----
    __syncthreads();
    {
        const int r = lane >> 2, c2 = (lane & 3) * 2;
        #pragma unroll
        for (int mt = 0; mt < 2; mt++)
            #pragma unroll
            for (int nt = 0; nt < 8; nt++) {
                *(__nv_bfloat162*)&Ms[(wm * 32 + mt * 16 + r)     * MST + n0 + nt * 8 + c2] =
                    __floats2bfloat162_rn(acc[mt][nt][0], acc[mt][nt][1]);
                *(__nv_bfloat162*)&Ms[(wm * 32 + mt * 16 + r + 8) * MST + n0 + nt * 8 + c2] =
                    __floats2bfloat162_rn(acc[mt][nt][2], acc[mt][nt][3]);
            }
    }
    __syncthreads();

    // ---- pairwise L1 via max/min pipe split + guarded exp ----
    // warp w -> samples w*4..w*4+3, lane = k1.
    // sum_k2 |m - v| = sum_k2 max(m,v) - sum_k2 min(m,v)  (exact identity)
    #pragma unroll
    for (int si = 0; si < 4; si++) {
        const int s = warp * 4 + si;
        const __nv_bfloat16* Mrow = &Ms[s * MST];

        __align__(16) __nv_bfloat162 v[8];
        *(uint4*)&v[0] = *(const uint4*)&Mrow[lane * KD];
        *(uint4*)&v[4] = *(const uint4*)&Mrow[lane * KD + 8];

        __nv_bfloat162 P[8], Q[8];
        const __nv_bfloat162 z2 = __floats2bfloat162_rn(0.f, 0.f);
        #pragma unroll
        for (int j = 0; j < 8; j++) { P[j] = z2; Q[j] = z2; }

        #pragma unroll 4
        for (int k2 = 0; k2 < NK; k2++) {
            __align__(16) __nv_bfloat162 m[8];
            *(uint4*)&m[0] = *(const uint4*)&Mrow[k2 * KD];      // broadcast
            *(uint4*)&m[4] = *(const uint4*)&Mrow[k2 * KD + 8];
            #pragma unroll
            for (int j = 0; j < 8; j++) {
                P[j] = __hadd2(P[j], __hmax2(m[j], v[j]));   // alu (max) + fma (add)
                Q[j] = __hadd2(Q[j], __hmin2(m[j], v[j]));   // alu (min) + fma (add)
            }
        }

        __nv_bfloat162 a8[8];
        #pragma unroll
        for (int j = 0; j < 8; j++) a8[j] = __hsub2(P[j], Q[j]);

        __nv_bfloat162 mn2 = a8[0];
        #pragma unroll
        for (int j = 1; j < 8; j++) mn2 = __hmin2(mn2, a8[j]);
        float2 mnf = __bfloat1622float2(mn2);
        float mn = fminf(mnf.x, mnf.y);

        float facc = 0.f;
        if (__any_sync(0xffffffffu, mn < 100.0f)) {   // exp(-100)=3.7e-44: faithful, ~never taken
            #pragma unroll
            for (int j = 0; j < 8; j++) {
                float2 f = __bfloat1622float2(a8[j]);
                if (f.x < 100.0f) facc += __expf(-f.x);
                if (f.y < 100.0f) facc += __expf(-f.y);
            }
        }
        out[(sbase + s) * OUTF + FDIM + lane] = facc;
    }
}

extern "C" void kernel_launch(void* const* d_in, const int* in_sizes, int n_in,
                              void* d_out, int out_size)
{
    const float* x = (const float*)d_in[0];
    const float* T = (const float*)d_in[1];
    if (n_in >= 2 && in_sizes[0] < in_sizes[1]) {
        const float* tmp = x; x = T; T = tmp;
    }
    float* out = (float*)d_out;

    cudaFuncSetAttribute(mbd_kernel,
                         cudaFuncAttributeMaxDynamicSharedMemorySize,
                         SMEM_BYTES);

    convT_kernel<<<(FDIM * NCOLS / 4) / 256, 256>>>(T);
    mbd_kernel<<<NBLK, NT, SMEM_BYTES>>>(x, out);
}